// round 1
// baseline (speedup 1.0000x reference)
#include <cuda_runtime.h>
#include <cuda_bf16.h>
#include <math.h>

#define Bv   8
#define Cv   768
#define Hv   28
#define Wv   28
#define Gv   6
#define GCv  128
#define NHv  12
#define HCv  64
#define Sv   784            // H*W
#define SCALEv 0.125f       // 64^-0.5
#define EPSv 1e-5f

typedef long long ll;

// ---------------- scratch (device globals; no allocation) ----------------
__device__ float g_q   [Bv * Cv * Sv];   // (B, C, S)
__device__ float g_grid[Bv * Gv * Sv * 2]; // (B*G, S, {px,py})
__device__ float g_xst [Bv * Sv * Cv];   // (B, S, C) sampled x2
__device__ float g_k   [Bv * Cv * Sv];   // (B, C, S)
__device__ float g_v   [Bv * Cv * Sv];   // (B, C, S)
__device__ float g_avt [Bv * Sv * Cv];   // (B, S, C) attn@V

// =========================================================================
// Generic NT GEMM: C[m,n] = alpha * sum_k A[m,k]*B[n,k] (+bias_m[m]) (+bias_n[n])
// Per-z bases: base = ptr + (z/zdiv)*s_hi + (z%zdiv)*s_lo
// Tiles 64x64x16, 256 threads, 4x4 per thread, smem stored K-major for
// float4 LDS in the inner loop.
// =========================================================================
__global__ __launch_bounds__(256)
void gemm_nt(const float* __restrict__ A, int lda, ll sAhi, ll sAlo,
             const float* __restrict__ B, int ldb, ll sBhi, ll sBlo,
             float* __restrict__ C, int ldc, ll sChi, ll sClo,
             int M, int N, int K, int zdiv,
             const float* __restrict__ bias_m,
             const float* __restrict__ bias_n,
             float alpha)
{
    const int z  = blockIdx.z;
    const int zh = z / zdiv, zl = z % zdiv;
    A += zh * sAhi + zl * sAlo;
    B += zh * sBhi + zl * sBlo;
    C += zh * sChi + zl * sClo;

    __shared__ float As[16][64 + 4];
    __shared__ float Bs[16][64 + 4];

    const int m0 = blockIdx.y * 64;
    const int n0 = blockIdx.x * 64;
    const int tid = threadIdx.x;
    const int tx = tid & 15;      // n dir
    const int ty = tid >> 4;      // m dir

    float acc[4][4];
#pragma unroll
    for (int i = 0; i < 4; i++)
#pragma unroll
        for (int j = 0; j < 4; j++) acc[i][j] = 0.f;

    const int r  = tid >> 2;        // 0..63
    const int kq = (tid & 3) * 4;   // 0,4,8,12

    for (int k0 = 0; k0 < K; k0 += 16) {
        // ---- load A tile (64 m x 16 k), float4 along k, store transposed
        {
            const int gm = m0 + r, gk = k0 + kq;
            float4 v = make_float4(0.f, 0.f, 0.f, 0.f);
            if (gm < M) {
                if (gk + 3 < K) {
                    v = *(const float4*)&A[(ll)gm * lda + gk];
                } else {
                    float t0 = (gk + 0 < K) ? A[(ll)gm * lda + gk + 0] : 0.f;
                    float t1 = (gk + 1 < K) ? A[(ll)gm * lda + gk + 1] : 0.f;
                    float t2 = (gk + 2 < K) ? A[(ll)gm * lda + gk + 2] : 0.f;
                    float t3 = (gk + 3 < K) ? A[(ll)gm * lda + gk + 3] : 0.f;
                    v = make_float4(t0, t1, t2, t3);
                }
            }
            As[kq + 0][r] = v.x; As[kq + 1][r] = v.y;
            As[kq + 2][r] = v.z; As[kq + 3][r] = v.w;
        }
        // ---- load B tile (64 n x 16 k)
        {
            const int gn = n0 + r, gk = k0 + kq;
            float4 v = make_float4(0.f, 0.f, 0.f, 0.f);
            if (gn < N) {
                if (gk + 3 < K) {
                    v = *(const float4*)&B[(ll)gn * ldb + gk];
                } else {
                    float t0 = (gk + 0 < K) ? B[(ll)gn * ldb + gk + 0] : 0.f;
                    float t1 = (gk + 1 < K) ? B[(ll)gn * ldb + gk + 1] : 0.f;
                    float t2 = (gk + 2 < K) ? B[(ll)gn * ldb + gk + 2] : 0.f;
                    float t3 = (gk + 3 < K) ? B[(ll)gn * ldb + gk + 3] : 0.f;
                    v = make_float4(t0, t1, t2, t3);
                }
            }
            Bs[kq + 0][r] = v.x; Bs[kq + 1][r] = v.y;
            Bs[kq + 2][r] = v.z; Bs[kq + 3][r] = v.w;
        }
        __syncthreads();

#pragma unroll
        for (int k = 0; k < 16; k++) {
            const float4 a = *(const float4*)&As[k][ty * 4];
            const float4 b = *(const float4*)&Bs[k][tx * 4];
            acc[0][0] += a.x * b.x; acc[0][1] += a.x * b.y; acc[0][2] += a.x * b.z; acc[0][3] += a.x * b.w;
            acc[1][0] += a.y * b.x; acc[1][1] += a.y * b.y; acc[1][2] += a.y * b.z; acc[1][3] += a.y * b.w;
            acc[2][0] += a.z * b.x; acc[2][1] += a.z * b.y; acc[2][2] += a.z * b.z; acc[2][3] += a.z * b.w;
            acc[3][0] += a.w * b.x; acc[3][1] += a.w * b.y; acc[3][2] += a.w * b.z; acc[3][3] += a.w * b.w;
        }
        __syncthreads();
    }

#pragma unroll
    for (int i = 0; i < 4; i++) {
        const int m = m0 + ty * 4 + i;
        if (m >= M) continue;
        const float bm = bias_m ? bias_m[m] : 0.f;
#pragma unroll
        for (int j = 0; j < 4; j++) {
            const int n = n0 + tx * 4 + j;
            if (n >= N) continue;
            float val = alpha * acc[i][j] + bm;
            if (bias_n) val += bias_n[n];
            C[(ll)m * ldc + n] = val;
        }
    }
}

// =========================================================================
// Fused: depthwise 5x5 conv -> LayerNorm(channels) -> GELU -> offset proj
//        -> tanh/scale -> sampling pixel coords.  Block = (h, bg)
// =========================================================================
__global__ __launch_bounds__(256)
void offset_kernel(const float* __restrict__ q,
                   const float* __restrict__ dw_w,
                   const float* __restrict__ dw_b,
                   const float* __restrict__ ln_g,
                   const float* __restrict__ ln_b,
                   const float* __restrict__ off_w,
                   float* __restrict__ gridbuf)
{
    const int h  = blockIdx.x;   // 0..27
    const int bg = blockIdx.y;   // 0..47
    const int tid = threadIdx.x;

    __shared__ float ts[GCv * Wv];          // 128 x 28
    __shared__ float ssum[Wv * 8], ssq[Wv * 8];
    __shared__ float s_mean[Wv], s_rstd[Wv];

    const float* qbase = q + (ll)bg * GCv * Sv;

    // depthwise conv (zero padded)
    for (int idx = tid; idx < GCv * Wv; idx += 256) {
        const int c = idx / Wv, x = idx % Wv;
        float accv = dw_b[c];
        const float* wrow = dw_w + c * 25;
        const float* qc = qbase + (ll)c * Sv;
#pragma unroll
        for (int dy = 0; dy < 5; dy++) {
            const int hh = h + dy - 2;
            if (hh < 0 || hh >= Hv) continue;
            const float* qrow = qc + hh * Wv;
#pragma unroll
            for (int dx = 0; dx < 5; dx++) {
                const int xx = x + dx - 2;
                if (xx >= 0 && xx < Wv)
                    accv += wrow[dy * 5 + dx] * __ldg(&qrow[xx]);
            }
        }
        ts[idx] = accv;
    }
    __syncthreads();

    // LN stats over channels (per x)
    if (tid < Wv * 8) {
        const int x = tid % Wv, part = tid / Wv;
        float s = 0.f, sq = 0.f;
        for (int c = part * 16; c < part * 16 + 16; c++) {
            const float v = ts[c * Wv + x];
            s += v; sq += v * v;
        }
        ssum[x * 8 + part] = s; ssq[x * 8 + part] = sq;
    }
    __syncthreads();
    if (tid < Wv) {
        float s = 0.f, sq = 0.f;
        for (int p = 0; p < 8; p++) { s += ssum[tid * 8 + p]; sq += ssq[tid * 8 + p]; }
        const float mu  = s * (1.f / GCv);
        const float var = sq * (1.f / GCv) - mu * mu;
        s_mean[tid] = mu;
        s_rstd[tid] = rsqrtf(var + EPSv);
    }
    __syncthreads();

    // normalize + GELU(exact)
    for (int idx = tid; idx < GCv * Wv; idx += 256) {
        const int c = idx / Wv, x = idx % Wv;
        const float v = (ts[idx] - s_mean[x]) * s_rstd[x] * ln_g[c] + ln_b[c];
        ts[idx] = 0.5f * v * (1.f + erff(v * 0.70710678118654752f));
    }
    __syncthreads();

    // offset projection (2 x 128 dot) -> tanh -> pixel coords
    if (tid < 2 * Wv) {
        const int o = tid / Wv;      // 0: y, 1: x
        const int x = tid % Wv;
        float s = 0.f;
        const float* w = off_w + o * GCv;
        for (int c = 0; c < GCv; c++) s += w[c] * ts[c * Wv + x];
        const float off = tanhf(s) * (2.0f / 28.0f);   // OFR*1/H == OFR*1/W
        const float ref = (float)(2 * (o == 0 ? h : x) + 1) * (1.0f / 28.0f) - 1.0f;
        const float pos = off + ref;
        const float pix = (pos + 1.0f) * 0.5f * 27.0f;
        // grid[...,0] = x-pixel, grid[...,1] = y-pixel
        gridbuf[((ll)bg * Sv + h * Wv + x) * 2 + (o == 0 ? 1 : 0)] = pix;
    }
}

// =========================================================================
// Bilinear gather: xs_t[b, p, c] = sample(x2[b, :, c], grid[b*G + c/128, p])
// Block = (p, b), threads over channels (coalesced).
// =========================================================================
__global__ __launch_bounds__(256)
void sample_kernel(const float* __restrict__ x2,
                   const float* __restrict__ gridbuf,
                   float* __restrict__ xst)
{
    const int p = blockIdx.x;   // 0..783
    const int b = blockIdx.y;   // 0..7
    const int tid = threadIdx.x;

    __shared__ float coords[Gv][2];
    if (tid < Gv * 2) {
        const int g = tid >> 1, o = tid & 1;
        coords[g][o] = gridbuf[((ll)(b * Gv + g) * Sv + p) * 2 + o];
    }
    __syncthreads();

    const float* xb = x2 + (ll)b * Sv * Cv;
    float* ob = xst + ((ll)b * Sv + p) * Cv;

    for (int c = tid; c < Cv; c += 256) {
        const int g = c >> 7;
        const float px = coords[g][0], py = coords[g][1];
        const float x0f = floorf(px), y0f = floorf(py);
        const int x0 = (int)x0f, y0 = (int)y0f;
        const float wx1 = px - x0f, wy1 = py - y0f;
        const float wx0 = 1.f - wx1, wy0 = 1.f - wy1;

        float r = 0.f;
#pragma unroll
        for (int dy = 0; dy < 2; dy++) {
            const int yy = y0 + dy;
            if (yy < 0 || yy >= Hv) continue;
            const float wy = dy ? wy1 : wy0;
#pragma unroll
            for (int dx = 0; dx < 2; dx++) {
                const int xx = x0 + dx;
                if (xx < 0 || xx >= Wv) continue;
                const float wx = dx ? wx1 : wx0;
                r += wy * wx * __ldg(&xb[(ll)(yy * Wv + xx) * Cv + c]);
            }
        }
        ob[c] = r;
    }
}

// =========================================================================
// Attention logits: attn[bh, n, m] = SCALE * sum_d q[bh][d,n] * k[bh][d,m]
// TT form, K = 64 in one shot.  64x64 tile, 256 threads, 4x4/thread.
// =========================================================================
__global__ __launch_bounds__(256)
void logits_kernel(const float* __restrict__ q,
                   const float* __restrict__ k,
                   float* __restrict__ attn)
{
    const int bh = blockIdx.z;
    const float* A = q + (ll)bh * HCv * Sv;   // [64][784]
    const float* Bm = k + (ll)bh * HCv * Sv;  // [64][784]
    float* C = attn + (ll)bh * Sv * Sv;

    const int n0 = blockIdx.y * 64;
    const int m0 = blockIdx.x * 64;
    const int tid = threadIdx.x;

    __shared__ float Qs[64][68];
    __shared__ float Ks[64][68];

#pragma unroll
    for (int i = 0; i < 4; i++) {
        const int idx4 = tid + i * 256;        // 0..1023
        const int d  = idx4 >> 4;
        const int nq = (idx4 & 15) * 4;
        // Q tile
        {
            const int gn = n0 + nq;
            float4 v = make_float4(0.f, 0.f, 0.f, 0.f);
            if (gn + 3 < Sv) v = *(const float4*)&A[(ll)d * Sv + gn];
            else {
                float t0 = (gn + 0 < Sv) ? A[(ll)d * Sv + gn + 0] : 0.f;
                float t1 = (gn + 1 < Sv) ? A[(ll)d * Sv + gn + 1] : 0.f;
                float t2 = (gn + 2 < Sv) ? A[(ll)d * Sv + gn + 2] : 0.f;
                float t3 = (gn + 3 < Sv) ? A[(ll)d * Sv + gn + 3] : 0.f;
                v = make_float4(t0, t1, t2, t3);
            }
            *(float4*)&Qs[d][nq] = v;
        }
        // K tile
        {
            const int gm = m0 + nq;
            float4 v = make_float4(0.f, 0.f, 0.f, 0.f);
            if (gm + 3 < Sv) v = *(const float4*)&Bm[(ll)d * Sv + gm];
            else {
                float t0 = (gm + 0 < Sv) ? Bm[(ll)d * Sv + gm + 0] : 0.f;
                float t1 = (gm + 1 < Sv) ? Bm[(ll)d * Sv + gm + 1] : 0.f;
                float t2 = (gm + 2 < Sv) ? Bm[(ll)d * Sv + gm + 2] : 0.f;
                float t3 = (gm + 3 < Sv) ? Bm[(ll)d * Sv + gm + 3] : 0.f;
                v = make_float4(t0, t1, t2, t3);
            }
            *(float4*)&Ks[d][nq] = v;
        }
    }
    __syncthreads();

    const int tx = tid & 15;   // m dir
    const int ty = tid >> 4;   // n dir
    float acc[4][4];
#pragma unroll
    for (int i = 0; i < 4; i++)
#pragma unroll
        for (int j = 0; j < 4; j++) acc[i][j] = 0.f;

#pragma unroll
    for (int d = 0; d < 64; d++) {
        const float4 a = *(const float4*)&Qs[d][ty * 4];
        const float4 b = *(const float4*)&Ks[d][tx * 4];
        acc[0][0] += a.x * b.x; acc[0][1] += a.x * b.y; acc[0][2] += a.x * b.z; acc[0][3] += a.x * b.w;
        acc[1][0] += a.y * b.x; acc[1][1] += a.y * b.y; acc[1][2] += a.y * b.z; acc[1][3] += a.y * b.w;
        acc[2][0] += a.z * b.x; acc[2][1] += a.z * b.y; acc[2][2] += a.z * b.z; acc[2][3] += a.z * b.w;
        acc[3][0] += a.w * b.x; acc[3][1] += a.w * b.y; acc[3][2] += a.w * b.z; acc[3][3] += a.w * b.w;
    }

#pragma unroll
    for (int i = 0; i < 4; i++) {
        const int n = n0 + ty * 4 + i;
        if (n >= Sv) continue;
#pragma unroll
        for (int j = 0; j < 4; j++) {
            const int m = m0 + tx * 4 + j;
            if (m >= Sv) continue;
            C[(ll)n * Sv + m] = acc[i][j] * SCALEv;
        }
    }
}

// =========================================================================
// In-place row softmax over 784 elements.  One block / row, 256 threads.
// =========================================================================
__global__ __launch_bounds__(256)
void softmax_kernel(float* __restrict__ a)
{
    float* p = a + (ll)blockIdx.x * Sv;
    const int tid = threadIdx.x;

    float v[4];
    float mx = -1e30f;
#pragma unroll
    for (int j = 0; j < 4; j++) {
        const int i = tid + j * 256;
        v[j] = (i < Sv) ? p[i] : -1e30f;
        mx = fmaxf(mx, v[j]);
    }
    __shared__ float red[8], red2[8];
#pragma unroll
    for (int o = 16; o > 0; o >>= 1) mx = fmaxf(mx, __shfl_xor_sync(0xffffffffu, mx, o));
    if ((tid & 31) == 0) red[tid >> 5] = mx;
    __syncthreads();
    mx = red[0];
#pragma unroll
    for (int w = 1; w < 8; w++) mx = fmaxf(mx, red[w]);

    float s = 0.f;
#pragma unroll
    for (int j = 0; j < 4; j++) {
        v[j] = expf(v[j] - mx);
        if (tid + j * 256 < Sv) s += v[j];
    }
#pragma unroll
    for (int o = 16; o > 0; o >>= 1) s += __shfl_xor_sync(0xffffffffu, s, o);
    if ((tid & 31) == 0) red2[tid >> 5] = s;
    __syncthreads();
    s = 0.f;
#pragma unroll
    for (int w = 0; w < 8; w++) s += red2[w];
    const float inv = 1.f / s;

#pragma unroll
    for (int j = 0; j < 4; j++) {
        const int i = tid + j * 256;
        if (i < Sv) p[i] = v[j] * inv;
    }
}

// =========================================================================
extern "C" void kernel_launch(void* const* d_in, const int* in_sizes, int n_in,
                              void* d_out, int out_size)
{
    (void)in_sizes; (void)n_in; (void)out_size;

    const float* x1   = (const float*)d_in[0];
    const float* x2   = (const float*)d_in[1];
    const float* dw_w = (const float*)d_in[2];
    const float* dw_b = (const float*)d_in[3];
    const float* ln_g = (const float*)d_in[4];
    const float* ln_b = (const float*)d_in[5];
    const float* offw = (const float*)d_in[6];
    const float* wq   = (const float*)d_in[7];
    const float* bq   = (const float*)d_in[8];
    const float* wk   = (const float*)d_in[9];
    const float* bk   = (const float*)d_in[10];
    const float* wv   = (const float*)d_in[11];
    const float* bv   = (const float*)d_in[12];
    const float* wo   = (const float*)d_in[13];
    const float* bo   = (const float*)d_in[14];

    float* out  = (float*)d_out;                       // (B, S, C)
    float* attn = out + (ll)Bv * Sv * Cv;              // (B*NH, S, S)

    void *pq_, *pgrid_, *pxst_, *pk_, *pv_, *pavt_;
    cudaGetSymbolAddress(&pq_,   g_q);
    cudaGetSymbolAddress(&pgrid_, g_grid);
    cudaGetSymbolAddress(&pxst_, g_xst);
    cudaGetSymbolAddress(&pk_,   g_k);
    cudaGetSymbolAddress(&pv_,   g_v);
    cudaGetSymbolAddress(&pavt_, g_avt);
    float* pq   = (float*)pq_;
    float* pgrid= (float*)pgrid_;
    float* pxst = (float*)pxst_;
    float* pk   = (float*)pk_;
    float* pv   = (float*)pv_;
    float* pavt = (float*)pavt_;

    const dim3 thr(256);
    const ll SC = (ll)Sv * Cv;   // 602112
    const ll CS = (ll)Cv * Sv;   // 602112
    const ll SS = (ll)Sv * Sv;   // 614656

    // 1. q[b,o,s] = wq[o,:] . x1[b,s,:] + bq[o]
    gemm_nt<<<dim3(13, 12, Bv), thr>>>(wq, Cv, 0, 0,
                                       x1, Cv, SC, 0,
                                       pq, Sv, CS, 0,
                                       Cv, Sv, Cv, 1, bq, nullptr, 1.f);

    // 2. dwconv+LN+GELU+offset -> sample coords
    offset_kernel<<<dim3(Hv, Bv * Gv), thr>>>(pq, dw_w, dw_b, ln_g, ln_b, offw, pgrid);

    // 3. bilinear gather -> xs_t (B, S, C)
    sample_kernel<<<dim3(Sv, Bv), thr>>>(x2, pgrid, pxst);

    // 4/5. k, v
    gemm_nt<<<dim3(13, 12, Bv), thr>>>(wk, Cv, 0, 0,
                                       pxst, Cv, SC, 0,
                                       pk, Sv, CS, 0,
                                       Cv, Sv, Cv, 1, bk, nullptr, 1.f);
    gemm_nt<<<dim3(13, 12, Bv), thr>>>(wv, Cv, 0, 0,
                                       pxst, Cv, SC, 0,
                                       pv, Sv, CS, 0,
                                       Cv, Sv, Cv, 1, bv, nullptr, 1.f);

    // 6. attention logits (into d_out attn region)
    logits_kernel<<<dim3(13, 13, Bv * NHv), thr>>>(pq, pk, attn);

    // 7. softmax rows (in place)
    softmax_kernel<<<Bv * NHv * Sv, thr>>>(attn);

    // 8. AV: avt[b, n, h*64+d] = sum_m attn[bh,n,m] * v[b,h*64+d,m]
    gemm_nt<<<dim3(1, 13, Bv * NHv), thr>>>(attn, Sv, (ll)NHv * SS, SS,
                                            pv, Sv, CS, (ll)HCv * Sv,
                                            pavt, Cv, SC, HCv,
                                            Sv, HCv, Sv, NHv, nullptr, nullptr, 1.f);

    // 9. out[b,s,oo] = avt[b,s,:] . wo[oo,:] + bo[oo]
    gemm_nt<<<dim3(12, 13, Bv), thr>>>(pavt, Cv, SC, 0,
                                       wo, Cv, 0, 0,
                                       out, Cv, SC, 0,
                                       Sv, Cv, Cv, 1, nullptr, bo, 1.f);
}

// round 3
// speedup vs baseline: 1.5894x; 1.5894x over previous
#include <cuda_runtime.h>
#include <cuda_bf16.h>
#include <math.h>
#include <stdint.h>

#define Bv   8
#define Cv   768
#define Hv   28
#define Wv   28
#define Gv   6
#define GCv  128
#define NHv  12
#define HCv  64
#define Sv   784
#define Nv   (Bv * Sv)      // 6272
#define SCALEv 0.125f
#define EPSv 1e-5f

typedef long long ll;

// ---------------- scratch (device globals; no allocation) ----------------
__device__ float g_q2 [Cv * Nv];            // (768, 6272)
__device__ float g_k2 [Cv * Nv];
__device__ float g_v2 [Cv * Nv];
__device__ float g_grid[Bv * Gv * Sv * 2];
__device__ float g_xst [Nv * Cv];           // (6272, 768)
__device__ float g_avt [Nv * Cv];           // (6272, 768)

__device__ __nv_bfloat16 g_x1h [Nv * Cv],  g_x1l [Nv * Cv];
__device__ __nv_bfloat16 g_xsth[Nv * Cv],  g_xstl[Nv * Cv];
__device__ __nv_bfloat16 g_avth[Nv * Cv],  g_avtl[Nv * Cv];
__device__ __nv_bfloat16 g_wqh [Cv * Cv],  g_wql [Cv * Cv];
__device__ __nv_bfloat16 g_wkh [Cv * Cv],  g_wkl [Cv * Cv];
__device__ __nv_bfloat16 g_wvh [Cv * Cv],  g_wvl [Cv * Cv];
__device__ __nv_bfloat16 g_woh [Cv * Cv],  g_wol [Cv * Cv];

// ======================= PTX helpers (sm_80-portable) =====================
__device__ __forceinline__ uint32_t smem_u32(const void* p) {
    uint32_t a;
    asm("{ .reg .u64 t; cvta.to.shared.u64 t, %1; cvt.u32.u64 %0, t; }" : "=r"(a) : "l"(p));
    return a;
}
__device__ __forceinline__ void cpa16(uint32_t dst, const void* src) {
    asm volatile("cp.async.cg.shared.global [%0], [%1], 16;" :: "r"(dst), "l"(src));
}
#define CP_COMMIT() asm volatile("cp.async.commit_group;" ::: "memory")
#define CP_WAIT1()  asm volatile("cp.async.wait_group 1;" ::: "memory")

__device__ __forceinline__ void ldsm4(uint32_t* r, uint32_t addr) {
    asm volatile("ldmatrix.sync.aligned.m8n8.x4.shared.b16 {%0,%1,%2,%3}, [%4];"
        : "=r"(r[0]), "=r"(r[1]), "=r"(r[2]), "=r"(r[3]) : "r"(addr));
}
__device__ __forceinline__ void mma16816(float* c, const uint32_t* a, const uint32_t* b) {
    asm volatile(
        "mma.sync.aligned.m16n8k16.row.col.f32.bf16.bf16.f32 "
        "{%0,%1,%2,%3}, {%4,%5,%6,%7}, {%8,%9}, {%0,%1,%2,%3};"
        : "+f"(c[0]), "+f"(c[1]), "+f"(c[2]), "+f"(c[3])
        : "r"(a[0]), "r"(a[1]), "r"(a[2]), "r"(a[3]), "r"(b[0]), "r"(b[1]));
}

// =========================================================================
// bf16x3 warp-MMA GEMM:  C[M x N] (row-major ldc) = A(MxK) . B(NxK)^T (+bias)
// A,B bf16 hi/lo splits, K contiguous.  M,N multiples of 128, K mult of 32.
// CTA tile 128x128, 8 warps (32m x 64n each), K-chunk 32, cp.async 2-stage.
// smem tile rows padded to 40 bf16 (80B) -> conflict-free ldmatrix.
// =========================================================================
#define KC       32
#define TPAD     40
#define TILE_B   (128 * TPAD * 2)   // 10240 B per tile
#define STAGE_B  (4 * TILE_B)       // 40960 B
#define MMA_SMEM (2 * STAGE_B)      // 81920 B

__global__ void __launch_bounds__(256, 1)
mma_gemm(const __nv_bfloat16* __restrict__ Ah, const __nv_bfloat16* __restrict__ Al,
         const __nv_bfloat16* __restrict__ Bh, const __nv_bfloat16* __restrict__ Bl,
         float* __restrict__ C, int K, int ldc,
         const float* __restrict__ bias_m, const float* __restrict__ bias_n)
{
    extern __shared__ char smem[];
    const uint32_t sb = smem_u32(smem);
    const int tid = threadIdx.x;
    const int wid = tid >> 5, lane = tid & 31;

    const int m0 = blockIdx.y * 128;
    const int n0 = blockIdx.x * 128;

    const __nv_bfloat16* srcs[4] = {
        Ah + (ll)m0 * K, Al + (ll)m0 * K,
        Bh + (ll)n0 * K, Bl + (ll)n0 * K };

    const int NCk = K / KC;

    // per-thread load coords (2 uint4 per tile)
    const int l_row0 = tid >> 1;                 // unused pattern; use idx scheme below

    float acc[2][8][4];
#pragma unroll
    for (int i = 0; i < 2; i++)
#pragma unroll
        for (int j = 0; j < 8; j++)
#pragma unroll
            for (int r = 0; r < 4; r++) acc[i][j][r] = 0.f;

    // ---- issue loads for chunk c into stage (c&1)
    auto issue = [&](int c) {
        const uint32_t st = sb + (uint32_t)(c & 1) * STAGE_B;
        const ll kb = (ll)c * KC;
#pragma unroll
        for (int t = 0; t < 4; t++) {
            const __nv_bfloat16* src = srcs[t];
            const uint32_t tb = st + t * TILE_B;
#pragma unroll
            for (int it = 0; it < 2; it++) {
                const int idx = tid + it * 256;      // 0..511
                const int row = idx >> 2;
                const int q   = idx & 3;
                cpa16(tb + row * 80 + q * 16, src + (ll)row * K + kb + q * 8);
            }
        }
    };

    issue(0); CP_COMMIT();

    // warp fragment base coords
    const int wm = (wid & 3) * 32;          // warp m offset in tile
    const int wn = (wid >> 2) * 64;         // warp n offset in tile
    const int rsel = lane & 7;
    const int aRow = wm + rsel + ((lane >> 3) & 1) * 8;       // + mf*16
    const int aColB = ((lane >> 4) & 1) * 16;                 // byte offset (+kst*32)
    const int bRow = wn + rsel + ((lane >> 4) & 1) * 8;       // + nf2*16
    const int bColB = ((lane >> 3) & 1) * 16;                 // byte offset (+kst*32)

    for (int c = 0; c < NCk; c++) {
        if (c + 1 < NCk) issue(c + 1);
        CP_COMMIT();
        CP_WAIT1();
        __syncthreads();

        const uint32_t st = sb + (uint32_t)(c & 1) * STAGE_B;
#pragma unroll
        for (int kst = 0; kst < 2; kst++) {
            uint32_t ah[2][4], al[2][4];
#pragma unroll
            for (int mf = 0; mf < 2; mf++) {
                const uint32_t ra = st + (aRow + mf * 16) * 80 + kst * 32 + aColB;
                ldsm4(ah[mf], ra);
                ldsm4(al[mf], ra + TILE_B);
            }
            uint32_t bh[8][2], bl[8][2];
#pragma unroll
            for (int nf2 = 0; nf2 < 4; nf2++) {
                const uint32_t rb = st + 2 * TILE_B + (bRow + nf2 * 16) * 80 + kst * 32 + bColB;
                uint32_t t4[4];
                ldsm4(t4, rb);
                bh[nf2 * 2][0] = t4[0]; bh[nf2 * 2][1] = t4[1];
                bh[nf2 * 2 + 1][0] = t4[2]; bh[nf2 * 2 + 1][1] = t4[3];
                ldsm4(t4, rb + TILE_B);
                bl[nf2 * 2][0] = t4[0]; bl[nf2 * 2][1] = t4[1];
                bl[nf2 * 2 + 1][0] = t4[2]; bl[nf2 * 2 + 1][1] = t4[3];
            }
#pragma unroll
            for (int mf = 0; mf < 2; mf++)
#pragma unroll
                for (int nf = 0; nf < 8; nf++) {
                    mma16816(acc[mf][nf], ah[mf], bh[nf]);
                    mma16816(acc[mf][nf], ah[mf], bl[nf]);
                    mma16816(acc[mf][nf], al[mf], bh[nf]);
                }
        }
        __syncthreads();
    }

    // ---- epilogue: direct STG with biases
#pragma unroll
    for (int mf = 0; mf < 2; mf++) {
        const int r0 = m0 + wm + mf * 16 + (lane >> 2);
        const int r1 = r0 + 8;
        const float bm0 = bias_m ? __ldg(&bias_m[r0]) : 0.f;
        const float bm1 = bias_m ? __ldg(&bias_m[r1]) : 0.f;
#pragma unroll
        for (int nf = 0; nf < 8; nf++) {
            const int col = n0 + wn + nf * 8 + (lane & 3) * 2;
            float bn0 = 0.f, bn1 = 0.f;
            if (bias_n) { bn0 = __ldg(&bias_n[col]); bn1 = __ldg(&bias_n[col + 1]); }
            const float* a = acc[mf][nf];
            C[(ll)r0 * ldc + col]     = a[0] + bm0 + bn0;
            C[(ll)r0 * ldc + col + 1] = a[1] + bm0 + bn1;
            C[(ll)r1 * ldc + col]     = a[2] + bm1 + bn0;
            C[(ll)r1 * ldc + col + 1] = a[3] + bm1 + bn1;
        }
    }
    (void)l_row0;
}

// =========================================================================
// fp32 -> bf16 hi/lo split
// =========================================================================
__global__ __launch_bounds__(256)
void split_bf16(const float* __restrict__ in, __nv_bfloat16* __restrict__ hi,
                __nv_bfloat16* __restrict__ lo, int n)
{
    const int i = blockIdx.x * 256 + threadIdx.x;
    if (i < n) {
        const float x = in[i];
        const __nv_bfloat16 h = __float2bfloat16(x);
        hi[i] = h;
        lo[i] = __float2bfloat16(x - __bfloat162float(h));
    }
}

// =========================================================================
// SIMT NT GEMM (AV):  C = A . B^T, z-batched
// =========================================================================
__global__ __launch_bounds__(256)
void gemm_nt(const float* __restrict__ A, int lda, ll sAhi, ll sAlo,
             const float* __restrict__ B, int ldb, ll sBhi, ll sBlo,
             float* __restrict__ C, int ldc, ll sChi, ll sClo,
             int M, int N, int K, int zdiv, float alpha)
{
    const int z  = blockIdx.z;
    const int zh = z / zdiv, zl = z % zdiv;
    A += zh * sAhi + zl * sAlo;
    B += zh * sBhi + zl * sBlo;
    C += zh * sChi + zl * sClo;

    __shared__ float As[16][64 + 4];
    __shared__ float Bs[16][64 + 4];

    const int m0 = blockIdx.y * 64;
    const int n0 = blockIdx.x * 64;
    const int tid = threadIdx.x;
    const int tx = tid & 15;
    const int ty = tid >> 4;

    float acc[4][4];
#pragma unroll
    for (int i = 0; i < 4; i++)
#pragma unroll
        for (int j = 0; j < 4; j++) acc[i][j] = 0.f;

    const int r  = tid >> 2;
    const int kq = (tid & 3) * 4;

    for (int k0 = 0; k0 < K; k0 += 16) {
        {
            const int gm = m0 + r, gk = k0 + kq;
            float4 v = make_float4(0.f, 0.f, 0.f, 0.f);
            if (gm < M) {
                if (gk + 3 < K) v = *(const float4*)&A[(ll)gm * lda + gk];
                else {
                    float t0 = (gk + 0 < K) ? A[(ll)gm * lda + gk + 0] : 0.f;
                    float t1 = (gk + 1 < K) ? A[(ll)gm * lda + gk + 1] : 0.f;
                    float t2 = (gk + 2 < K) ? A[(ll)gm * lda + gk + 2] : 0.f;
                    float t3 = (gk + 3 < K) ? A[(ll)gm * lda + gk + 3] : 0.f;
                    v = make_float4(t0, t1, t2, t3);
                }
            }
            As[kq + 0][r] = v.x; As[kq + 1][r] = v.y;
            As[kq + 2][r] = v.z; As[kq + 3][r] = v.w;
        }
        {
            const int gn = n0 + r, gk = k0 + kq;
            float4 v = make_float4(0.f, 0.f, 0.f, 0.f);
            if (gn < N) {
                if (gk + 3 < K) v = *(const float4*)&B[(ll)gn * ldb + gk];
                else {
                    float t0 = (gk + 0 < K) ? B[(ll)gn * ldb + gk + 0] : 0.f;
                    float t1 = (gk + 1 < K) ? B[(ll)gn * ldb + gk + 1] : 0.f;
                    float t2 = (gk + 2 < K) ? B[(ll)gn * ldb + gk + 2] : 0.f;
                    float t3 = (gk + 3 < K) ? B[(ll)gn * ldb + gk + 3] : 0.f;
                    v = make_float4(t0, t1, t2, t3);
                }
            }
            Bs[kq + 0][r] = v.x; Bs[kq + 1][r] = v.y;
            Bs[kq + 2][r] = v.z; Bs[kq + 3][r] = v.w;
        }
        __syncthreads();

#pragma unroll
        for (int k = 0; k < 16; k++) {
            const float4 a = *(const float4*)&As[k][ty * 4];
            const float4 b = *(const float4*)&Bs[k][tx * 4];
            acc[0][0] += a.x * b.x; acc[0][1] += a.x * b.y; acc[0][2] += a.x * b.z; acc[0][3] += a.x * b.w;
            acc[1][0] += a.y * b.x; acc[1][1] += a.y * b.y; acc[1][2] += a.y * b.z; acc[1][3] += a.y * b.w;
            acc[2][0] += a.z * b.x; acc[2][1] += a.z * b.y; acc[2][2] += a.z * b.z; acc[2][3] += a.z * b.w;
            acc[3][0] += a.w * b.x; acc[3][1] += a.w * b.y; acc[3][2] += a.w * b.z; acc[3][3] += a.w * b.w;
        }
        __syncthreads();
    }

#pragma unroll
    for (int i = 0; i < 4; i++) {
        const int m = m0 + ty * 4 + i;
        if (m >= M) continue;
#pragma unroll
        for (int j = 0; j < 4; j++) {
            const int n = n0 + tx * 4 + j;
            if (n >= N) continue;
            C[(ll)m * ldc + n] = alpha * acc[i][j];
        }
    }
}

// =========================================================================
// Fused dwconv5x5 -> LN -> GELU -> offset proj -> sampling coords
// q2 layout: (768, 6272)
// =========================================================================
__global__ __launch_bounds__(256)
void offset_kernel(const float* __restrict__ q2,
                   const float* __restrict__ dw_w,
                   const float* __restrict__ dw_b,
                   const float* __restrict__ ln_g,
                   const float* __restrict__ ln_b,
                   const float* __restrict__ off_w,
                   float* __restrict__ gridbuf)
{
    const int h  = blockIdx.x;
    const int bg = blockIdx.y;            // b*G + g
    const int b = bg / Gv, g = bg % Gv;
    const int tid = threadIdx.x;

    __shared__ float ts[GCv * Wv];
    __shared__ float ssum[Wv * 8], ssq[Wv * 8];
    __shared__ float s_mean[Wv], s_rstd[Wv];

    const float* qbase = q2 + (ll)(g * GCv) * Nv + b * Sv;

    for (int idx = tid; idx < GCv * Wv; idx += 256) {
        const int c = idx / Wv, x = idx % Wv;
        float accv = dw_b[c];
        const float* wrow = dw_w + c * 25;
        const float* qc = qbase + (ll)c * Nv;
#pragma unroll
        for (int dy = 0; dy < 5; dy++) {
            const int hh = h + dy - 2;
            if (hh < 0 || hh >= Hv) continue;
            const float* qrow = qc + hh * Wv;
#pragma unroll
            for (int dx = 0; dx < 5; dx++) {
                const int xx = x + dx - 2;
                if (xx >= 0 && xx < Wv)
                    accv += wrow[dy * 5 + dx] * __ldg(&qrow[xx]);
            }
        }
        ts[idx] = accv;
    }
    __syncthreads();

    if (tid < Wv * 8) {
        const int x = tid % Wv, part = tid / Wv;
        float s = 0.f, sq = 0.f;
        for (int c = part * 16; c < part * 16 + 16; c++) {
            const float v = ts[c * Wv + x];
            s += v; sq += v * v;
        }
        ssum[x * 8 + part] = s; ssq[x * 8 + part] = sq;
    }
    __syncthreads();
    if (tid < Wv) {
        float s = 0.f, sq = 0.f;
        for (int p = 0; p < 8; p++) { s += ssum[tid * 8 + p]; sq += ssq[tid * 8 + p]; }
        const float mu  = s * (1.f / GCv);
        const float var = sq * (1.f / GCv) - mu * mu;
        s_mean[tid] = mu;
        s_rstd[tid] = rsqrtf(var + EPSv);
    }
    __syncthreads();

    for (int idx = tid; idx < GCv * Wv; idx += 256) {
        const int c = idx / Wv, x = idx % Wv;
        const float v = (ts[idx] - s_mean[x]) * s_rstd[x] * ln_g[c] + ln_b[c];
        ts[idx] = 0.5f * v * (1.f + erff(v * 0.70710678118654752f));
    }
    __syncthreads();

    if (tid < 2 * Wv) {
        const int o = tid / Wv;
        const int x = tid % Wv;
        float s = 0.f;
        const float* w = off_w + o * GCv;
        for (int c = 0; c < GCv; c++) s += w[c] * ts[c * Wv + x];
        const float off = tanhf(s) * (2.0f / 28.0f);
        const float ref = (float)(2 * (o == 0 ? h : x) + 1) * (1.0f / 28.0f) - 1.0f;
        const float pix = ((off + ref) + 1.0f) * 0.5f * 27.0f;
        gridbuf[((ll)bg * Sv + h * Wv + x) * 2 + (o == 0 ? 1 : 0)] = pix;
    }
}

// =========================================================================
// Bilinear gather -> xst (B*S, C)
// =========================================================================
__global__ __launch_bounds__(256)
void sample_kernel(const float* __restrict__ x2,
                   const float* __restrict__ gridbuf,
                   float* __restrict__ xst)
{
    const int p = blockIdx.x;
    const int b = blockIdx.y;
    const int tid = threadIdx.x;

    __shared__ float coords[Gv][2];
    if (tid < Gv * 2) {
        const int g = tid >> 1, o = tid & 1;
        coords[g][o] = gridbuf[((ll)(b * Gv + g) * Sv + p) * 2 + o];
    }
    __syncthreads();

    const float* xb = x2 + (ll)b * Sv * Cv;
    float* ob = xst + ((ll)b * Sv + p) * Cv;

    for (int c = tid; c < Cv; c += 256) {
        const int g = c >> 7;
        const float px = coords[g][0], py = coords[g][1];
        const float x0f = floorf(px), y0f = floorf(py);
        const int x0 = (int)x0f, y0 = (int)y0f;
        const float wx1 = px - x0f, wy1 = py - y0f;
        const float wx0 = 1.f - wx1, wy0 = 1.f - wy1;

        float r = 0.f;
#pragma unroll
        for (int dy = 0; dy < 2; dy++) {
            const int yy = y0 + dy;
            if (yy < 0 || yy >= Hv) continue;
            const float wy = dy ? wy1 : wy0;
#pragma unroll
            for (int dx = 0; dx < 2; dx++) {
                const int xx = x0 + dx;
                if (xx < 0 || xx >= Wv) continue;
                const float wx = dx ? wx1 : wx0;
                r += wy * wx * __ldg(&xb[(ll)(yy * Wv + xx) * Cv + c]);
            }
        }
        ob[c] = r;
    }
}

// =========================================================================
// Attention logits (q2/k2 layout, row stride Nv)
// =========================================================================
__global__ __launch_bounds__(256)
void logits_kernel(const float* __restrict__ q2,
                   const float* __restrict__ k2,
                   float* __restrict__ attn)
{
    const int bh = blockIdx.z;
    const int b = bh / NHv, h = bh % NHv;
    const float* A  = q2 + (ll)(h * HCv) * Nv + b * Sv;
    const float* Bm = k2 + (ll)(h * HCv) * Nv + b * Sv;
    float* C = attn + (ll)bh * Sv * Sv;

    const int n0 = blockIdx.y * 64;
    const int m0 = blockIdx.x * 64;
    const int tid = threadIdx.x;

    __shared__ float Qs[64][68];
    __shared__ float Ks[64][68];

#pragma unroll
    for (int i = 0; i < 4; i++) {
        const int idx4 = tid + i * 256;
        const int d  = idx4 >> 4;
        const int nq = (idx4 & 15) * 4;
        {
            const int gn = n0 + nq;
            float4 v = make_float4(0.f, 0.f, 0.f, 0.f);
            if (gn + 3 < Sv) v = *(const float4*)&A[(ll)d * Nv + gn];
            else {
                float t0 = (gn + 0 < Sv) ? A[(ll)d * Nv + gn + 0] : 0.f;
                float t1 = (gn + 1 < Sv) ? A[(ll)d * Nv + gn + 1] : 0.f;
                float t2 = (gn + 2 < Sv) ? A[(ll)d * Nv + gn + 2] : 0.f;
                float t3 = (gn + 3 < Sv) ? A[(ll)d * Nv + gn + 3] : 0.f;
                v = make_float4(t0, t1, t2, t3);
            }
            *(float4*)&Qs[d][nq] = v;
        }
        {
            const int gm = m0 + nq;
            float4 v = make_float4(0.f, 0.f, 0.f, 0.f);
            if (gm + 3 < Sv) v = *(const float4*)&Bm[(ll)d * Nv + gm];
            else {
                float t0 = (gm + 0 < Sv) ? Bm[(ll)d * Nv + gm + 0] : 0.f;
                float t1 = (gm + 1 < Sv) ? Bm[(ll)d * Nv + gm + 1] : 0.f;
                float t2 = (gm + 2 < Sv) ? Bm[(ll)d * Nv + gm + 2] : 0.f;
                float t3 = (gm + 3 < Sv) ? Bm[(ll)d * Nv + gm + 3] : 0.f;
                v = make_float4(t0, t1, t2, t3);
            }
            *(float4*)&Ks[d][nq] = v;
        }
    }
    __syncthreads();

    const int tx = tid & 15;
    const int ty = tid >> 4;
    float acc[4][4];
#pragma unroll
    for (int i = 0; i < 4; i++)
#pragma unroll
        for (int j = 0; j < 4; j++) acc[i][j] = 0.f;

#pragma unroll
    for (int d = 0; d < 64; d++) {
        const float4 a = *(const float4*)&Qs[d][ty * 4];
        const float4 b = *(const float4*)&Ks[d][tx * 4];
        acc[0][0] += a.x * b.x; acc[0][1] += a.x * b.y; acc[0][2] += a.x * b.z; acc[0][3] += a.x * b.w;
        acc[1][0] += a.y * b.x; acc[1][1] += a.y * b.y; acc[1][2] += a.y * b.z; acc[1][3] += a.y * b.w;
        acc[2][0] += a.z * b.x; acc[2][1] += a.z * b.y; acc[2][2] += a.z * b.z; acc[2][3] += a.z * b.w;
        acc[3][0] += a.w * b.x; acc[3][1] += a.w * b.y; acc[3][2] += a.w * b.z; acc[3][3] += a.w * b.w;
    }

#pragma unroll
    for (int i = 0; i < 4; i++) {
        const int n = n0 + ty * 4 + i;
        if (n >= Sv) continue;
#pragma unroll
        for (int j = 0; j < 4; j++) {
            const int m = m0 + tx * 4 + j;
            if (m >= Sv) continue;
            C[(ll)n * Sv + m] = acc[i][j] * SCALEv;
        }
    }
}

// =========================================================================
// In-place row softmax over 784
// =========================================================================
__global__ __launch_bounds__(256)
void softmax_kernel(float* __restrict__ a)
{
    float* p = a + (ll)blockIdx.x * Sv;
    const int tid = threadIdx.x;

    float v[4];
    float mx = -1e30f;
#pragma unroll
    for (int j = 0; j < 4; j++) {
        const int i = tid + j * 256;
        v[j] = (i < Sv) ? p[i] : -1e30f;
        mx = fmaxf(mx, v[j]);
    }
    __shared__ float red[8], red2[8];
#pragma unroll
    for (int o = 16; o > 0; o >>= 1) mx = fmaxf(mx, __shfl_xor_sync(0xffffffffu, mx, o));
    if ((tid & 31) == 0) red[tid >> 5] = mx;
    __syncthreads();
    mx = red[0];
#pragma unroll
    for (int w = 1; w < 8; w++) mx = fmaxf(mx, red[w]);

    float s = 0.f;
#pragma unroll
    for (int j = 0; j < 4; j++) {
        v[j] = expf(v[j] - mx);
        if (tid + j * 256 < Sv) s += v[j];
    }
#pragma unroll
    for (int o = 16; o > 0; o >>= 1) s += __shfl_xor_sync(0xffffffffu, s, o);
    if ((tid & 31) == 0) red2[tid >> 5] = s;
    __syncthreads();
    s = 0.f;
#pragma unroll
    for (int w = 0; w < 8; w++) s += red2[w];
    const float inv = 1.f / s;

#pragma unroll
    for (int j = 0; j < 4; j++) {
        const int i = tid + j * 256;
        if (i < Sv) p[i] = v[j] * inv;
    }
}

// =========================================================================
extern "C" void kernel_launch(void* const* d_in, const int* in_sizes, int n_in,
                              void* d_out, int out_size)
{
    (void)in_sizes; (void)n_in; (void)out_size;

    const float* x1   = (const float*)d_in[0];
    const float* x2   = (const float*)d_in[1];
    const float* dw_w = (const float*)d_in[2];
    const float* dw_b = (const float*)d_in[3];
    const float* ln_g = (const float*)d_in[4];
    const float* ln_b = (const float*)d_in[5];
    const float* offw = (const float*)d_in[6];
    const float* wq   = (const float*)d_in[7];
    const float* bq   = (const float*)d_in[8];
    const float* wk   = (const float*)d_in[9];
    const float* bk   = (const float*)d_in[10];
    const float* wv   = (const float*)d_in[11];
    const float* bv   = (const float*)d_in[12];
    const float* wo   = (const float*)d_in[13];
    const float* bo   = (const float*)d_in[14];

    float* out  = (float*)d_out;
    float* attn = out + (ll)Bv * Sv * Cv;

    cudaFuncSetAttribute(mma_gemm, cudaFuncAttributeMaxDynamicSharedMemorySize, MMA_SMEM);

    void *p;
#define SYM(name, var) cudaGetSymbolAddress(&p, name); float* var = (float*)p;
#define SYMB(name, var) cudaGetSymbolAddress(&p, name); __nv_bfloat16* var = (__nv_bfloat16*)p;
    SYM(g_q2, pq2)  SYM(g_k2, pk2)  SYM(g_v2, pv2)
    SYM(g_grid, pgrid) SYM(g_xst, pxst) SYM(g_avt, pavt)
    SYMB(g_x1h, x1h)  SYMB(g_x1l, x1l)
    SYMB(g_xsth, xsth) SYMB(g_xstl, xstl)
    SYMB(g_avth, avth) SYMB(g_avtl, avtl)
    SYMB(g_wqh, wqh) SYMB(g_wql, wql)
    SYMB(g_wkh, wkh) SYMB(g_wkl, wkl)
    SYMB(g_wvh, wvh) SYMB(g_wvl, wvl)
    SYMB(g_woh, woh) SYMB(g_wol, wol)
#undef SYM
#undef SYMB

    const int NW = Cv * Cv;        // 589824
    const int NX = Nv * Cv;        // 4816896
    const dim3 thr(256);

    // ---- splits of weights + x1
    split_bf16<<<(NW + 255) / 256, thr>>>(wq, wqh, wql, NW);
    split_bf16<<<(NW + 255) / 256, thr>>>(wk, wkh, wkl, NW);
    split_bf16<<<(NW + 255) / 256, thr>>>(wv, wvh, wvl, NW);
    split_bf16<<<(NW + 255) / 256, thr>>>(wo, woh, wol, NW);
    split_bf16<<<(NX + 255) / 256, thr>>>(x1, x1h, x1l, NX);

    // ---- q2 = wq @ x1^T  (768 x 6272)
    mma_gemm<<<dim3(Nv / 128, Cv / 128), thr, MMA_SMEM>>>(
        wqh, wql, x1h, x1l, pq2, Cv, Nv, bq, nullptr);

    // ---- offsets + sampling
    offset_kernel<<<dim3(Hv, Bv * Gv), thr>>>(pq2, dw_w, dw_b, ln_g, ln_b, offw, pgrid);
    sample_kernel<<<dim3(Sv, Bv), thr>>>(x2, pgrid, pxst);
    split_bf16<<<(NX + 255) / 256, thr>>>(pxst, xsth, xstl, NX);

    // ---- k2, v2
    mma_gemm<<<dim3(Nv / 128, Cv / 128), thr, MMA_SMEM>>>(
        wkh, wkl, xsth, xstl, pk2, Cv, Nv, bk, nullptr);
    mma_gemm<<<dim3(Nv / 128, Cv / 128), thr, MMA_SMEM>>>(
        wvh, wvl, xsth, xstl, pv2, Cv, Nv, bv, nullptr);

    // ---- attention
    logits_kernel<<<dim3(13, 13, Bv * NHv), thr>>>(pq2, pk2, attn);
    softmax_kernel<<<Bv * NHv * Sv, thr>>>(attn);

    // ---- AV: avt[(b*784+n), h*64+d] = sum_m attn[bh,n,m] * v2[h*64+d, b*784+m]
    const ll SS = (ll)Sv * Sv;
    gemm_nt<<<dim3(1, 13, Bv * NHv), thr>>>(
        attn, Sv, (ll)NHv * SS, SS,
        pv2, Nv, (ll)Sv, (ll)HCv * Nv,
        pavt, Cv, (ll)Sv * Cv, (ll)HCv,
        Sv, HCv, Sv, NHv, 1.f);

    // ---- out = avt @ wo^T + bo  (6272 x 768) directly into d_out
    split_bf16<<<(NX + 255) / 256, thr>>>(pavt, avth, avtl, NX);
    mma_gemm<<<dim3(Cv / 128, Nv / 128), thr, MMA_SMEM>>>(
        avth, avtl, woh, wol, out, Cv, Cv, nullptr, bo);
}

// round 4
// speedup vs baseline: 2.1059x; 1.3250x over previous
#include <cuda_runtime.h>
#include <cuda_bf16.h>
#include <math.h>
#include <stdint.h>

#define Bv   8
#define Cv   768
#define Hv   28
#define Wv   28
#define Gv   6
#define GCv  128
#define NHv  12
#define HCv  64
#define Sv   784
#define Nv   (Bv * Sv)      // 6272
#define SCALEv 0.125f
#define EPSv 1e-5f
#define PADE 4096

typedef long long ll;

// ---------------- scratch (device globals; no allocation) ----------------
__device__ float g_q2 [Cv * Nv];                       // (768, 6272) fp32 (offset path)
__device__ float g_grid[Bv * Gv * Sv * 2];

__device__ __nv_bfloat16 g_qh [Cv * Nv + PADE], g_ql [Cv * Nv + PADE];   // (C, Nv)
__device__ __nv_bfloat16 g_kh [Cv * Nv + PADE], g_kl [Cv * Nv + PADE];
__device__ __nv_bfloat16 g_vh [Cv * Nv + PADE], g_vl [Cv * Nv + PADE];
__device__ __nv_bfloat16 g_x1h [Nv * Cv], g_x1l [Nv * Cv];               // (Nv, C)
__device__ __nv_bfloat16 g_xsth[Nv * Cv], g_xstl[Nv * Cv];
__device__ __nv_bfloat16 g_avth[Nv * Cv], g_avtl[Nv * Cv];
__device__ __nv_bfloat16 g_wqh [Cv * Cv], g_wql [Cv * Cv];
__device__ __nv_bfloat16 g_wkh [Cv * Cv], g_wkl [Cv * Cv];
__device__ __nv_bfloat16 g_wvh [Cv * Cv], g_wvl [Cv * Cv];
__device__ __nv_bfloat16 g_woh [Cv * Cv], g_wol [Cv * Cv];

// ======================= PTX helpers (sm_80-portable) =====================
__device__ __forceinline__ uint32_t smem_u32(const void* p) {
    uint32_t a;
    asm("{ .reg .u64 t; cvta.to.shared.u64 t, %1; cvt.u32.u64 %0, t; }" : "=r"(a) : "l"(p));
    return a;
}
__device__ __forceinline__ void cpa16(uint32_t dst, const void* src) {
    asm volatile("cp.async.cg.shared.global [%0], [%1], 16;" :: "r"(dst), "l"(src));
}
#define CP_COMMIT() asm volatile("cp.async.commit_group;" ::: "memory")
#define CP_WAIT1()  asm volatile("cp.async.wait_group 1;" ::: "memory")
#define CP_WAIT0()  asm volatile("cp.async.wait_group 0;" ::: "memory")

__device__ __forceinline__ void ldsm4(uint32_t* r, uint32_t addr) {
    asm volatile("ldmatrix.sync.aligned.m8n8.x4.shared.b16 {%0,%1,%2,%3}, [%4];"
        : "=r"(r[0]), "=r"(r[1]), "=r"(r[2]), "=r"(r[3]) : "r"(addr));
}
__device__ __forceinline__ void ldsm4t(uint32_t* r, uint32_t addr) {
    asm volatile("ldmatrix.sync.aligned.m8n8.x4.trans.shared.b16 {%0,%1,%2,%3}, [%4];"
        : "=r"(r[0]), "=r"(r[1]), "=r"(r[2]), "=r"(r[3]) : "r"(addr));
}
__device__ __forceinline__ void mma16816(float* c, const uint32_t* a, const uint32_t* b) {
    asm volatile(
        "mma.sync.aligned.m16n8k16.row.col.f32.bf16.bf16.f32 "
        "{%0,%1,%2,%3}, {%4,%5,%6,%7}, {%8,%9}, {%0,%1,%2,%3};"
        : "+f"(c[0]), "+f"(c[1]), "+f"(c[2]), "+f"(c[3])
        : "r"(a[0]), "r"(a[1]), "r"(a[2]), "r"(a[3]), "r"(b[0]), "r"(b[1]));
}
__device__ __forceinline__ void store_hilo(__nv_bfloat16* Hp, __nv_bfloat16* Lp,
                                           ll idx, float a, float b) {
    const __nv_bfloat16 ha = __float2bfloat16(a), hb = __float2bfloat16(b);
    __nv_bfloat162 hv; hv.x = ha; hv.y = hb;
    *(__nv_bfloat162*)(Hp + idx) = hv;
    __nv_bfloat162 lv;
    lv.x = __float2bfloat16(a - __bfloat162float(ha));
    lv.y = __float2bfloat16(b - __bfloat162float(hb));
    *(__nv_bfloat162*)(Lp + idx) = lv;
}

// =========================================================================
// bf16x3 warp-MMA GEMM:  C[M x N] = A(MxK) . B(NxK)^T (+bias_m +bias_n)
// outputs: optional fp32 Cf, optional bf16 hi/lo (Chi/Clo), all row-major ldc
// M,N multiples of 128, K mult of 32.
// =========================================================================
#define KC       32
#define TPAD     40
#define TILE_B   (128 * TPAD * 2)
#define STAGE_B  (4 * TILE_B)
#define MMA_SMEM (2 * STAGE_B)

__global__ void __launch_bounds__(256, 1)
mma_gemm(const __nv_bfloat16* __restrict__ Ah, const __nv_bfloat16* __restrict__ Al,
         const __nv_bfloat16* __restrict__ Bh, const __nv_bfloat16* __restrict__ Bl,
         float* __restrict__ Cf,
         __nv_bfloat16* __restrict__ Chi, __nv_bfloat16* __restrict__ Clo,
         int K, int ldc,
         const float* __restrict__ bias_m, const float* __restrict__ bias_n)
{
    extern __shared__ char smem[];
    const uint32_t sb = smem_u32(smem);
    const int tid = threadIdx.x;
    const int wid = tid >> 5, lane = tid & 31;

    const int m0 = blockIdx.y * 128;
    const int n0 = blockIdx.x * 128;

    const __nv_bfloat16* srcs[4] = {
        Ah + (ll)m0 * K, Al + (ll)m0 * K,
        Bh + (ll)n0 * K, Bl + (ll)n0 * K };

    const int NCk = K / KC;

    float acc[2][8][4];
#pragma unroll
    for (int i = 0; i < 2; i++)
#pragma unroll
        for (int j = 0; j < 8; j++)
#pragma unroll
            for (int r = 0; r < 4; r++) acc[i][j][r] = 0.f;

    auto issue = [&](int c) {
        const uint32_t st = sb + (uint32_t)(c & 1) * STAGE_B;
        const ll kb = (ll)c * KC;
#pragma unroll
        for (int t = 0; t < 4; t++) {
            const __nv_bfloat16* src = srcs[t];
            const uint32_t tb = st + t * TILE_B;
#pragma unroll
            for (int it = 0; it < 2; it++) {
                const int idx = tid + it * 256;
                const int row = idx >> 2;
                const int q   = idx & 3;
                cpa16(tb + row * 80 + q * 16, src + (ll)row * K + kb + q * 8);
            }
        }
    };

    issue(0); CP_COMMIT();

    const int wm = (wid & 3) * 32;
    const int wn = (wid >> 2) * 64;
    const int rsel = lane & 7;
    const int aRow = wm + rsel + ((lane >> 3) & 1) * 8;
    const int aColB = ((lane >> 4) & 1) * 16;
    const int bRow = wn + rsel + ((lane >> 4) & 1) * 8;
    const int bColB = ((lane >> 3) & 1) * 16;

    for (int c = 0; c < NCk; c++) {
        if (c + 1 < NCk) issue(c + 1);
        CP_COMMIT();
        CP_WAIT1();
        __syncthreads();

        const uint32_t st = sb + (uint32_t)(c & 1) * STAGE_B;
#pragma unroll
        for (int kst = 0; kst < 2; kst++) {
            uint32_t ah[2][4], al[2][4];
#pragma unroll
            for (int mf = 0; mf < 2; mf++) {
                const uint32_t ra = st + (aRow + mf * 16) * 80 + kst * 32 + aColB;
                ldsm4(ah[mf], ra);
                ldsm4(al[mf], ra + TILE_B);
            }
            uint32_t bh[8][2], bl[8][2];
#pragma unroll
            for (int nf2 = 0; nf2 < 4; nf2++) {
                const uint32_t rb = st + 2 * TILE_B + (bRow + nf2 * 16) * 80 + kst * 32 + bColB;
                uint32_t t4[4];
                ldsm4(t4, rb);
                bh[nf2 * 2][0] = t4[0]; bh[nf2 * 2][1] = t4[1];
                bh[nf2 * 2 + 1][0] = t4[2]; bh[nf2 * 2 + 1][1] = t4[3];
                ldsm4(t4, rb + TILE_B);
                bl[nf2 * 2][0] = t4[0]; bl[nf2 * 2][1] = t4[1];
                bl[nf2 * 2 + 1][0] = t4[2]; bl[nf2 * 2 + 1][1] = t4[3];
            }
#pragma unroll
            for (int mf = 0; mf < 2; mf++)
#pragma unroll
                for (int nf = 0; nf < 8; nf++) {
                    mma16816(acc[mf][nf], ah[mf], bh[nf]);
                    mma16816(acc[mf][nf], ah[mf], bl[nf]);
                    mma16816(acc[mf][nf], al[mf], bh[nf]);
                }
        }
        __syncthreads();
    }

#pragma unroll
    for (int mf = 0; mf < 2; mf++) {
        const int r0 = m0 + wm + mf * 16 + (lane >> 2);
        const int r1 = r0 + 8;
        const float bm0 = bias_m ? __ldg(&bias_m[r0]) : 0.f;
        const float bm1 = bias_m ? __ldg(&bias_m[r1]) : 0.f;
#pragma unroll
        for (int nf = 0; nf < 8; nf++) {
            const int col = n0 + wn + nf * 8 + (lane & 3) * 2;
            float bn0 = 0.f, bn1 = 0.f;
            if (bias_n) { bn0 = __ldg(&bias_n[col]); bn1 = __ldg(&bias_n[col + 1]); }
            const float* a = acc[mf][nf];
            const float v00 = a[0] + bm0 + bn0, v01 = a[1] + bm0 + bn1;
            const float v10 = a[2] + bm1 + bn0, v11 = a[3] + bm1 + bn1;
            const ll i0 = (ll)r0 * ldc + col;
            const ll i1 = (ll)r1 * ldc + col;
            if (Cf) {
                float2 f0; f0.x = v00; f0.y = v01; *(float2*)&Cf[i0] = f0;
                float2 f1; f1.x = v10; f1.y = v11; *(float2*)&Cf[i1] = f1;
            }
            if (Chi) {
                store_hilo(Chi, Clo, i0, v00, v01);
                store_hilo(Chi, Clo, i1, v10, v11);
            }
        }
    }
}

// =========================================================================
// fp32 -> bf16 hi/lo split
// =========================================================================
__global__ __launch_bounds__(256)
void split_bf16(const float* __restrict__ in, __nv_bfloat16* __restrict__ hi,
                __nv_bfloat16* __restrict__ lo, int n)
{
    const int i = blockIdx.x * 256 + threadIdx.x;
    if (i < n) {
        const float x = in[i];
        const __nv_bfloat16 h = __float2bfloat16(x);
        hi[i] = h;
        lo[i] = __float2bfloat16(x - __bfloat162float(h));
    }
}

// =========================================================================
// Logits: attn[bh, i, j] = SCALE * sum_d q[d,i] * k[d,j]   (bf16x3 mma)
// q,k in (C, Nv) hi/lo; fragments via ldmatrix.trans.  Tile 128x128, K=64.
// =========================================================================
#define LROWB 272
#define LTILE (64 * LROWB)        // 17408
#define LSMEM (4 * LTILE)         // 69632

__global__ void __launch_bounds__(256, 1)
logits_mma(const __nv_bfloat16* __restrict__ qh, const __nv_bfloat16* __restrict__ ql,
           const __nv_bfloat16* __restrict__ kh, const __nv_bfloat16* __restrict__ kl,
           float* __restrict__ attn)
{
    extern __shared__ char smem[];
    const uint32_t sb = smem_u32(smem);
    const int tid = threadIdx.x;
    const int wid = tid >> 5, lane = tid & 31;
    const int bh = blockIdx.z, b = bh / NHv, h = bh % NHv;
    const int i0 = blockIdx.y * 128;
    const int j0 = blockIdx.x * 128;

    const ll off = (ll)(h * HCv) * Nv + (ll)b * Sv;
    const __nv_bfloat16* srcs[4] = { qh + off + i0, ql + off + i0,
                                     kh + off + j0, kl + off + j0 };
#pragma unroll
    for (int t = 0; t < 4; t++) {
        const uint32_t tb = sb + t * LTILE;
        const __nv_bfloat16* s = srcs[t];
#pragma unroll
        for (int it = 0; it < 4; it++) {
            const int idx = tid + it * 256;
            const int row = idx >> 4;        // d 0..63
            const int q   = idx & 15;        // 16B col chunk
            cpa16(tb + row * LROWB + q * 16, s + (ll)row * Nv + q * 8);
        }
    }
    CP_COMMIT(); CP_WAIT0();
    __syncthreads();

    const int wm = (wid & 3) * 32;       // i-dir
    const int wn = (wid >> 2) * 64;      // j-dir

    float acc[2][8][4];
#pragma unroll
    for (int i = 0; i < 2; i++)
#pragma unroll
        for (int j = 0; j < 8; j++)
#pragma unroll
            for (int r = 0; r < 4; r++) acc[i][j][r] = 0.f;

    const int arowk = (lane & 7) + ((lane >> 4) & 1) * 8;   // k-part for A
    const int acolm = wm + ((lane >> 3) & 1) * 8;           // m-part for A
    const int browk = (lane & 7) + ((lane >> 3) & 1) * 8;   // k-part for B
    const int bcoln = wn + ((lane >> 4) & 1) * 8;           // n-part for B

#pragma unroll
    for (int kst = 0; kst < 4; kst++) {
        uint32_t ah[2][4], al[2][4];
#pragma unroll
        for (int mf = 0; mf < 2; mf++) {
            const uint32_t ra = sb + (kst * 16 + arowk) * LROWB + (acolm + mf * 16) * 2;
            ldsm4t(ah[mf], ra);
            ldsm4t(al[mf], ra + LTILE);
        }
        uint32_t bhf[8][2], blf[8][2];
#pragma unroll
        for (int nf2 = 0; nf2 < 4; nf2++) {
            const uint32_t rb = sb + 2 * LTILE + (kst * 16 + browk) * LROWB + (bcoln + nf2 * 16) * 2;
            uint32_t t4[4];
            ldsm4t(t4, rb);
            bhf[nf2 * 2][0] = t4[0]; bhf[nf2 * 2][1] = t4[1];
            bhf[nf2 * 2 + 1][0] = t4[2]; bhf[nf2 * 2 + 1][1] = t4[3];
            ldsm4t(t4, rb + LTILE);
            blf[nf2 * 2][0] = t4[0]; blf[nf2 * 2][1] = t4[1];
            blf[nf2 * 2 + 1][0] = t4[2]; blf[nf2 * 2 + 1][1] = t4[3];
        }
#pragma unroll
        for (int mf = 0; mf < 2; mf++)
#pragma unroll
            for (int nf = 0; nf < 8; nf++) {
                mma16816(acc[mf][nf], ah[mf], bhf[nf]);
                mma16816(acc[mf][nf], ah[mf], blf[nf]);
                mma16816(acc[mf][nf], al[mf], bhf[nf]);
            }
    }

    float* Cp = attn + (ll)bh * Sv * Sv;
#pragma unroll
    for (int mf = 0; mf < 2; mf++) {
        const int r0 = i0 + wm + mf * 16 + (lane >> 2);
        const int r1 = r0 + 8;
#pragma unroll
        for (int nf = 0; nf < 8; nf++) {
            const int col = j0 + wn + nf * 8 + (lane & 3) * 2;
            if (col >= Sv) continue;
            const float* a = acc[mf][nf];
            if (r0 < Sv) {
                float2 f; f.x = a[0] * SCALEv; f.y = a[1] * SCALEv;
                *(float2*)&Cp[(ll)r0 * Sv + col] = f;
            }
            if (r1 < Sv) {
                float2 f; f.x = a[2] * SCALEv; f.y = a[3] * SCALEv;
                *(float2*)&Cp[(ll)r1 * Sv + col] = f;
            }
        }
    }
}

// =========================================================================
// AV: avt[(b*784+n), h*64+d] = sum_m attn[bh,n,m] * v[h*64+d, b*784+m]
// attn fp32 read + in-kernel hi/lo conversion; v hi/lo via cp.async.
// Tile 128n x 64d, K chunks of 32 (25 chunks over padded 800).
// =========================================================================
#define AVROWB 80

__global__ void __launch_bounds__(256, 1)
av_mma(const float* __restrict__ attn,
       const __nv_bfloat16* __restrict__ vh, const __nv_bfloat16* __restrict__ vl,
       __nv_bfloat16* __restrict__ avth, __nv_bfloat16* __restrict__ avtl)
{
    __shared__ char smc[2 * 128 * AVROWB + 2 * 64 * AVROWB];   // 30720
    const uint32_t sb = smem_u32(smc);
    const uint32_t sAh = sb, sAl = sb + 128 * AVROWB;
    const uint32_t sBh = sb + 2 * 128 * AVROWB, sBl = sBh + 64 * AVROWB;

    const int tid = threadIdx.x;
    const int wid = tid >> 5, lane = tid & 31;
    const int bh = blockIdx.y, b = bh / NHv, h = bh % NHv;
    const int n0 = blockIdx.x * 128;

    const float* Ap = attn + (ll)bh * Sv * Sv;
    const __nv_bfloat16* vbh = vh + (ll)(h * HCv) * Nv + (ll)b * Sv;
    const __nv_bfloat16* vbl = vl + (ll)(h * HCv) * Nv + (ll)b * Sv;

    float acc[2][4][4];
#pragma unroll
    for (int i = 0; i < 2; i++)
#pragma unroll
        for (int j = 0; j < 4; j++)
#pragma unroll
            for (int r = 0; r < 4; r++) acc[i][j][r] = 0.f;

    const int wm = (wid & 3) * 32;     // n
    const int wn = (wid >> 2) * 32;    // d
    const int rsel = lane & 7;
    const int aRow = wm + rsel + ((lane >> 3) & 1) * 8;
    const int aColB = ((lane >> 4) & 1) * 16;
    const int bRow = wn + rsel + ((lane >> 4) & 1) * 8;
    const int bColB = ((lane >> 3) & 1) * 16;

    // B load coords (one pass: 64 rows x 4 chunks)
    const int vrow = tid >> 2;
    const int vq   = tid & 3;

    for (int kc = 0; kc < 25; kc++) {
        const int kb = kc * 32;
        // --- B: v hi/lo via cp.async
        cpa16(sBh + vrow * AVROWB + vq * 16, vbh + (ll)vrow * Nv + kb + vq * 8);
        cpa16(sBl + vrow * AVROWB + vq * 16, vbl + (ll)vrow * Nv + kb + vq * 8);
        // --- A: attn fp32 -> hi/lo in smem
#pragma unroll
        for (int it = 0; it < 4; it++) {
            const int idx4 = tid + it * 256;
            const int row = idx4 >> 3;
            const int qq  = idx4 & 7;
            const int gn = n0 + row;
            const int gk = kb + qq * 4;
            float4 v = make_float4(0.f, 0.f, 0.f, 0.f);
            if (gn < Sv && gk < Sv)
                v = *(const float4*)&Ap[(ll)gn * Sv + gk];
            const __nv_bfloat16 h0 = __float2bfloat16(v.x), h1 = __float2bfloat16(v.y);
            const __nv_bfloat16 h2 = __float2bfloat16(v.z), h3 = __float2bfloat16(v.w);
            __nv_bfloat162 p01, p23, q01, q23;
            p01.x = h0; p01.y = h1; p23.x = h2; p23.y = h3;
            q01.x = __float2bfloat16(v.x - __bfloat162float(h0));
            q01.y = __float2bfloat16(v.y - __bfloat162float(h1));
            q23.x = __float2bfloat16(v.z - __bfloat162float(h2));
            q23.y = __float2bfloat16(v.w - __bfloat162float(h3));
            uint2 hw, lw;
            hw.x = *(uint32_t*)&p01; hw.y = *(uint32_t*)&p23;
            lw.x = *(uint32_t*)&q01; lw.y = *(uint32_t*)&q23;
            *(uint2*)(smc + (sAh - sb) + row * AVROWB + qq * 8) = hw;
            *(uint2*)(smc + (sAl - sb) + row * AVROWB + qq * 8) = lw;
        }
        CP_COMMIT(); CP_WAIT0();
        __syncthreads();

#pragma unroll
        for (int kst = 0; kst < 2; kst++) {
            uint32_t ah[2][4], al[2][4];
#pragma unroll
            for (int mf = 0; mf < 2; mf++) {
                const uint32_t ra = sAh + (aRow + mf * 16) * AVROWB + kst * 32 + aColB;
                ldsm4(ah[mf], ra);
                ldsm4(al[mf], ra + 128 * AVROWB);
            }
            uint32_t bhf[4][2], blf[4][2];
#pragma unroll
            for (int nf2 = 0; nf2 < 2; nf2++) {
                const uint32_t rb = sBh + (bRow + nf2 * 16) * AVROWB + kst * 32 + bColB;
                uint32_t t4[4];
                ldsm4(t4, rb);
                bhf[nf2 * 2][0] = t4[0]; bhf[nf2 * 2][1] = t4[1];
                bhf[nf2 * 2 + 1][0] = t4[2]; bhf[nf2 * 2 + 1][1] = t4[3];
                ldsm4(t4, rb + 64 * AVROWB);
                blf[nf2 * 2][0] = t4[0]; blf[nf2 * 2][1] = t4[1];
                blf[nf2 * 2 + 1][0] = t4[2]; blf[nf2 * 2 + 1][1] = t4[3];
            }
#pragma unroll
            for (int mf = 0; mf < 2; mf++)
#pragma unroll
                for (int nf = 0; nf < 4; nf++) {
                    mma16816(acc[mf][nf], ah[mf], bhf[nf]);
                    mma16816(acc[mf][nf], ah[mf], blf[nf]);
                    mma16816(acc[mf][nf], al[mf], bhf[nf]);
                }
        }
        __syncthreads();
    }

    // epilogue: avt (Nv, C) hi/lo
#pragma unroll
    for (int mf = 0; mf < 2; mf++) {
        const int r0 = n0 + wm + mf * 16 + (lane >> 2);
        const int r1 = r0 + 8;
#pragma unroll
        for (int nf = 0; nf < 4; nf++) {
            const int cold = wn + nf * 8 + (lane & 3) * 2;
            const ll colg = (ll)h * HCv + cold;
            const float* a = acc[mf][nf];
            if (r0 < Sv)
                store_hilo(avth, avtl, ((ll)b * Sv + r0) * Cv + colg, a[0], a[1]);
            if (r1 < Sv)
                store_hilo(avth, avtl, ((ll)b * Sv + r1) * Cv + colg, a[2], a[3]);
        }
    }
}

// =========================================================================
// Fused dwconv5x5 -> LN -> GELU -> offset proj -> sampling coords
// =========================================================================
__global__ __launch_bounds__(256)
void offset_kernel(const float* __restrict__ q2,
                   const float* __restrict__ dw_w,
                   const float* __restrict__ dw_b,
                   const float* __restrict__ ln_g,
                   const float* __restrict__ ln_b,
                   const float* __restrict__ off_w,
                   float* __restrict__ gridbuf)
{
    const int h  = blockIdx.x;
    const int bg = blockIdx.y;
    const int b = bg / Gv, g = bg % Gv;
    const int tid = threadIdx.x;

    __shared__ float ts[GCv * Wv];
    __shared__ float ssum[Wv * 8], ssq[Wv * 8];
    __shared__ float s_mean[Wv], s_rstd[Wv];

    const float* qbase = q2 + (ll)(g * GCv) * Nv + b * Sv;

    for (int idx = tid; idx < GCv * Wv; idx += 256) {
        const int c = idx / Wv, x = idx % Wv;
        float accv = dw_b[c];
        const float* wrow = dw_w + c * 25;
        const float* qc = qbase + (ll)c * Nv;
#pragma unroll
        for (int dy = 0; dy < 5; dy++) {
            const int hh = h + dy - 2;
            if (hh < 0 || hh >= Hv) continue;
            const float* qrow = qc + hh * Wv;
#pragma unroll
            for (int dx = 0; dx < 5; dx++) {
                const int xx = x + dx - 2;
                if (xx >= 0 && xx < Wv)
                    accv += wrow[dy * 5 + dx] * __ldg(&qrow[xx]);
            }
        }
        ts[idx] = accv;
    }
    __syncthreads();

    if (tid < Wv * 8) {
        const int x = tid % Wv, part = tid / Wv;
        float s = 0.f, sq = 0.f;
        for (int c = part * 16; c < part * 16 + 16; c++) {
            const float v = ts[c * Wv + x];
            s += v; sq += v * v;
        }
        ssum[x * 8 + part] = s; ssq[x * 8 + part] = sq;
    }
    __syncthreads();
    if (tid < Wv) {
        float s = 0.f, sq = 0.f;
        for (int p = 0; p < 8; p++) { s += ssum[tid * 8 + p]; sq += ssq[tid * 8 + p]; }
        const float mu  = s * (1.f / GCv);
        const float var = sq * (1.f / GCv) - mu * mu;
        s_mean[tid] = mu;
        s_rstd[tid] = rsqrtf(var + EPSv);
    }
    __syncthreads();

    for (int idx = tid; idx < GCv * Wv; idx += 256) {
        const int c = idx / Wv, x = idx % Wv;
        const float v = (ts[idx] - s_mean[x]) * s_rstd[x] * ln_g[c] + ln_b[c];
        ts[idx] = 0.5f * v * (1.f + erff(v * 0.70710678118654752f));
    }
    __syncthreads();

    if (tid < 2 * Wv) {
        const int o = tid / Wv;
        const int x = tid % Wv;
        float s = 0.f;
        const float* w = off_w + o * GCv;
        for (int c = 0; c < GCv; c++) s += w[c] * ts[c * Wv + x];
        const float off = tanhf(s) * (2.0f / 28.0f);
        const float ref = (float)(2 * (o == 0 ? h : x) + 1) * (1.0f / 28.0f) - 1.0f;
        const float pix = ((off + ref) + 1.0f) * 0.5f * 27.0f;
        gridbuf[((ll)bg * Sv + h * Wv + x) * 2 + (o == 0 ? 1 : 0)] = pix;
    }
}

// =========================================================================
// Bilinear gather -> xst hi/lo (Nv, C)
// =========================================================================
__global__ __launch_bounds__(256)
void sample_kernel(const float* __restrict__ x2,
                   const float* __restrict__ gridbuf,
                   __nv_bfloat16* __restrict__ xsth,
                   __nv_bfloat16* __restrict__ xstl)
{
    const int p = blockIdx.x;
    const int b = blockIdx.y;
    const int tid = threadIdx.x;

    __shared__ float coords[Gv][2];
    if (tid < Gv * 2) {
        const int g = tid >> 1, o = tid & 1;
        coords[g][o] = gridbuf[((ll)(b * Gv + g) * Sv + p) * 2 + o];
    }
    __syncthreads();

    const float* xb = x2 + (ll)b * Sv * Cv;
    const ll ob = ((ll)b * Sv + p) * Cv;

    for (int c = tid; c < Cv; c += 256) {
        const int g = c >> 7;
        const float px = coords[g][0], py = coords[g][1];
        const float x0f = floorf(px), y0f = floorf(py);
        const int x0 = (int)x0f, y0 = (int)y0f;
        const float wx1 = px - x0f, wy1 = py - y0f;
        const float wx0 = 1.f - wx1, wy0 = 1.f - wy1;

        float r = 0.f;
#pragma unroll
        for (int dy = 0; dy < 2; dy++) {
            const int yy = y0 + dy;
            if (yy < 0 || yy >= Hv) continue;
            const float wy = dy ? wy1 : wy0;
#pragma unroll
            for (int dx = 0; dx < 2; dx++) {
                const int xx = x0 + dx;
                if (xx < 0 || xx >= Wv) continue;
                const float wx = dx ? wx1 : wx0;
                r += wy * wx * __ldg(&xb[(ll)(yy * Wv + xx) * Cv + c]);
            }
        }
        const __nv_bfloat16 hv = __float2bfloat16(r);
        xsth[ob + c] = hv;
        xstl[ob + c] = __float2bfloat16(r - __bfloat162float(hv));
    }
}

// =========================================================================
// In-place row softmax over 784
// =========================================================================
__global__ __launch_bounds__(256)
void softmax_kernel(float* __restrict__ a)
{
    float* p = a + (ll)blockIdx.x * Sv;
    const int tid = threadIdx.x;

    float v[4];
    float mx = -1e30f;
#pragma unroll
    for (int j = 0; j < 4; j++) {
        const int i = tid + j * 256;
        v[j] = (i < Sv) ? p[i] : -1e30f;
        mx = fmaxf(mx, v[j]);
    }
    __shared__ float red[8], red2[8];
#pragma unroll
    for (int o = 16; o > 0; o >>= 1) mx = fmaxf(mx, __shfl_xor_sync(0xffffffffu, mx, o));
    if ((tid & 31) == 0) red[tid >> 5] = mx;
    __syncthreads();
    mx = red[0];
#pragma unroll
    for (int w = 1; w < 8; w++) mx = fmaxf(mx, red[w]);

    float s = 0.f;
#pragma unroll
    for (int j = 0; j < 4; j++) {
        v[j] = expf(v[j] - mx);
        if (tid + j * 256 < Sv) s += v[j];
    }
#pragma unroll
    for (int o = 16; o > 0; o >>= 1) s += __shfl_xor_sync(0xffffffffu, s, o);
    if ((tid & 31) == 0) red2[tid >> 5] = s;
    __syncthreads();
    s = 0.f;
#pragma unroll
    for (int w = 0; w < 8; w++) s += red2[w];
    const float inv = 1.f / s;

#pragma unroll
    for (int j = 0; j < 4; j++) {
        const int i = tid + j * 256;
        if (i < Sv) p[i] = v[j] * inv;
    }
}

// =========================================================================
extern "C" void kernel_launch(void* const* d_in, const int* in_sizes, int n_in,
                              void* d_out, int out_size)
{
    (void)in_sizes; (void)n_in; (void)out_size;

    const float* x1   = (const float*)d_in[0];
    const float* x2   = (const float*)d_in[1];
    const float* dw_w = (const float*)d_in[2];
    const float* dw_b = (const float*)d_in[3];
    const float* ln_g = (const float*)d_in[4];
    const float* ln_b = (const float*)d_in[5];
    const float* offw = (const float*)d_in[6];
    const float* wq   = (const float*)d_in[7];
    const float* bq   = (const float*)d_in[8];
    const float* wk   = (const float*)d_in[9];
    const float* bk   = (const float*)d_in[10];
    const float* wv   = (const float*)d_in[11];
    const float* bv   = (const float*)d_in[12];
    const float* wo   = (const float*)d_in[13];
    const float* bo   = (const float*)d_in[14];

    float* out  = (float*)d_out;
    float* attn = out + (ll)Bv * Sv * Cv;

    cudaFuncSetAttribute(mma_gemm, cudaFuncAttributeMaxDynamicSharedMemorySize, MMA_SMEM);
    cudaFuncSetAttribute(logits_mma, cudaFuncAttributeMaxDynamicSharedMemorySize, LSMEM);

    void *p;
#define SYM(name, var) cudaGetSymbolAddress(&p, name); float* var = (float*)p;
#define SYMB(name, var) cudaGetSymbolAddress(&p, name); __nv_bfloat16* var = (__nv_bfloat16*)p;
    SYM(g_q2, pq2)  SYM(g_grid, pgrid)
    SYMB(g_qh, qhp) SYMB(g_ql, qlp)
    SYMB(g_kh, khp) SYMB(g_kl, klp)
    SYMB(g_vh, vhp) SYMB(g_vl, vlp)
    SYMB(g_x1h, x1h)  SYMB(g_x1l, x1l)
    SYMB(g_xsth, xsth) SYMB(g_xstl, xstl)
    SYMB(g_avth, avth) SYMB(g_avtl, avtl)
    SYMB(g_wqh, wqh) SYMB(g_wql, wql)
    SYMB(g_wkh, wkh) SYMB(g_wkl, wkl)
    SYMB(g_wvh, wvh) SYMB(g_wvl, wvl)
    SYMB(g_woh, woh) SYMB(g_wol, wol)
#undef SYM
#undef SYMB

    const int NW = Cv * Cv;
    const int NX = Nv * Cv;
    const dim3 thr(256);

    // ---- splits: weights + x1
    split_bf16<<<(NW + 255) / 256, thr>>>(wq, wqh, wql, NW);
    split_bf16<<<(NW + 255) / 256, thr>>>(wk, wkh, wkl, NW);
    split_bf16<<<(NW + 255) / 256, thr>>>(wv, wvh, wvl, NW);
    split_bf16<<<(NW + 255) / 256, thr>>>(wo, woh, wol, NW);
    split_bf16<<<(NX + 255) / 256, thr>>>(x1, x1h, x1l, NX);

    // ---- q = wq @ x1^T : (C, Nv) fp32 + hi/lo
    mma_gemm<<<dim3(Nv / 128, Cv / 128), thr, MMA_SMEM>>>(
        wqh, wql, x1h, x1l, pq2, qhp, qlp, Cv, Nv, bq, nullptr);

    // ---- offsets + sampling (hi/lo out)
    offset_kernel<<<dim3(Hv, Bv * Gv), thr>>>(pq2, dw_w, dw_b, ln_g, ln_b, offw, pgrid);
    sample_kernel<<<dim3(Sv, Bv), thr>>>(x2, pgrid, xsth, xstl);

    // ---- k, v : (C, Nv) hi/lo only
    mma_gemm<<<dim3(Nv / 128, Cv / 128), thr, MMA_SMEM>>>(
        wkh, wkl, xsth, xstl, nullptr, khp, klp, Cv, Nv, bk, nullptr);
    mma_gemm<<<dim3(Nv / 128, Cv / 128), thr, MMA_SMEM>>>(
        wvh, wvl, xsth, xstl, nullptr, vhp, vlp, Cv, Nv, bv, nullptr);

    // ---- attention logits (tensor cores) + softmax
    logits_mma<<<dim3(7, 7, Bv * NHv), thr, LSMEM>>>(qhp, qlp, khp, klp, attn);
    softmax_kernel<<<Bv * NHv * Sv, thr>>>(attn);

    // ---- AV (tensor cores) -> avt hi/lo (Nv, C)
    av_mma<<<dim3(7, Bv * NHv), thr>>>(attn, vhp, vlp, avth, avtl);

    // ---- out = avt @ wo^T + bo -> d_out (Nv, C)
    mma_gemm<<<dim3(Cv / 128, Nv / 128), thr, MMA_SMEM>>>(
        avth, avtl, woh, wol, out, nullptr, nullptr, Cv, Cv, nullptr, bo);
}